// round 14
// baseline (speedup 1.0000x reference)
#include <cuda_runtime.h>
#include <cuda_bf16.h>
#include <cstdint>

// KANSplineLayer via tensor cores, bulk cp.async streaming.
// Order-3 Taylor: sum_g sigmoid(x+d_g) ~= 8*s + s'*m1 + (s''/2)*m2 + (s'''/6)*m3.
// One GEMM: out[b,o] = sum_{i,c} A[b,5i+c] * Bm[5i+c,o],
//   A  = (x, s', s''/2, s'''/6, s)   per (b,i)  [prep kernel, bf16]
//   Bm = (W^T[i,o], m1, m2, m3, 8)   per (i,o)  [built in smem from grid stream]
// R14: CTA copies its WHOLE 16KB grid tile via cp.async (no register staging,
// no intermediate barriers) -> in-flight bytes = resident CTAs x 16KB, breaking
// the register-bound MLP wall that pinned R10-R13 at ~2.4TB/s.

#define B_   16
#define IN_  1024
#define OUT_ 1024
#define G_   8
#define KC   5
#define AK   (KC * IN_)           // 5120
#define ITILE 16
#define OTILE 32
#define BROWS (KC * ITILE)        // 80
#define APITCH BROWS              // As [16][80]
#define BPITCH 40                 // Bs row pitch (bf16)

__device__ __align__(16) __nv_bfloat16 Wt_g[IN_ * OUT_];  // W^T bf16 (2MB)
__device__ __align__(16) __nv_bfloat16 A_g[B_ * AK];      // A matrix (160KB)

// ---------------- Kernel 1: prep (W transpose->bf16, A build, out zero) ----------------
__global__ __launch_bounds__(256) void kan_prep_kernel(
    const float* __restrict__ x, const float* __restrict__ w, float* __restrict__ out)
{
    const int bx = blockIdx.x, t = threadIdx.x;
    if (bx < 1024) {                       // W transpose: 32x32 tiles
        __shared__ float tile[32][33];
        const int tio = bx & 31, too = bx >> 5;
        const int tx = t & 31, ty = t >> 5;
        #pragma unroll
        for (int k = 0; k < 4; k++)
            tile[ty + 8 * k][tx] = w[(size_t)(too * 32 + ty + 8 * k) * IN_ + tio * 32 + tx];
        __syncthreads();
        #pragma unroll
        for (int k = 0; k < 4; k++)
            Wt_g[(size_t)(tio * 32 + ty + 8 * k) * OUT_ + too * 32 + tx] =
                __float2bfloat16(tile[tx][ty + 8 * k]);
    } else if (bx < 1088) {                // A build: 64 CTAs x 256 = 16384 (b,i)
        int idx = (bx - 1024) * 256 + t;
        int b = idx >> 10, i = idx & 1023;
        float xv = x[b * IN_ + i];
        float s  = __fdividef(1.f, 1.f + __expf(-xv));
        float d1 = s * (1.f - s);
        float om2s = 1.f - 2.f * s;
        float p6 = fmaf(6.f * s, s - 1.f, 1.f);
        __nv_bfloat16* ap = A_g + (size_t)b * AK + KC * i;
        ap[0] = __float2bfloat16(xv);
        ap[1] = __float2bfloat16(d1);
        ap[2] = __float2bfloat16(0.5f * d1 * om2s);
        ap[3] = __float2bfloat16((1.f / 6.f) * d1 * p6);
        ap[4] = __float2bfloat16(s);
    } else {                               // zero out: 16 CTAs x 256 float4
        int idx = (bx - 1088) * 256 + t;
        reinterpret_cast<float4*>(out)[idx] = make_float4(0.f, 0.f, 0.f, 0.f);
    }
}

// ---------------- Kernel 2: bulk-stream grid -> moments -> mma -> atomicAdd ----------------
__global__ __launch_bounds__(128, 8) void kan_mma_kernel(
    const float* __restrict__ grid, float* __restrict__ out)
{
    __shared__ __align__(16) float4        Gs[ITILE * OTILE * 2];   // 16KB grid tile
    __shared__ __align__(16) __nv_bfloat16 As[B_ * APITCH];         // 2.5KB
    __shared__ __align__(16) __nv_bfloat16 Bs[BROWS * BPITCH];      // 6.4KB

    const int t = threadIdx.x, lane = t & 31, warp = t >> 5;
    const int o0 = blockIdx.x * OTILE;
    const int i0 = blockIdx.y * ITILE;

    // ---- issue ALL copies up front: 16KB grid tile + 2.5KB A slab, zero reg cost ----
    {
        unsigned gdst = (unsigned)__cvta_generic_to_shared(Gs);
        const float* gsrc0 = grid + ((size_t)i0 * OUT_ + o0) * G_;
        #pragma unroll
        for (int k = 0; k < 8; k++) {                 // 1024 chunks of 16B
            int c   = t + 128 * k;
            int row = c >> 6, col = c & 63;           // 64 x 16B per i-row
            const float* src = gsrc0 + (size_t)row * (OUT_ * G_) + col * 4;
            asm volatile("cp.async.cg.shared.global [%0], [%1], 16;"
                         :: "r"(gdst + c * 16), "l"(src));
        }
        unsigned adst = (unsigned)__cvta_generic_to_shared(As);
        #pragma unroll
        for (int k = 0; k < 2; k++) {                 // 160 chunks of 16B
            int c = t + 128 * k;
            if (c < 160) {
                int r = c / 10, col = c % 10;
                const __nv_bfloat16* src = A_g + (size_t)r * AK + blockIdx.y * BROWS + col * 8;
                asm volatile("cp.async.cg.shared.global [%0], [%1], 16;"
                             :: "r"(adst + c * 16), "l"(src));
            }
        }
        asm volatile("cp.async.commit_group;" ::);
    }

    // W column values while copies fly (L2-resident, 4 per thread).
    __nv_bfloat16 wv[4];
    #pragma unroll
    for (int k = 0; k < 4; k++) {
        int idx = t + 128 * k;                        // (i,o) in tile
        int il = idx >> 5, o = idx & 31;
        wv[k] = Wt_g[(size_t)(i0 + il) * OUT_ + o0 + o];
    }

    asm volatile("cp.async.wait_group 0;" ::);
    __syncthreads();

    // ---- moments from smem -> Bs (each thread: 4 (i,o) pairs) ----
    #pragma unroll
    for (int k = 0; k < 4; k++) {
        int idx = t + 128 * k;
        int il = idx >> 5, o = idx & 31;
        float4 g0 = Gs[il * 64 + o * 2], g1 = Gs[il * 64 + o * 2 + 1];
        float d[8] = { g0.x, g0.y, g0.z, g0.w, g1.x, g1.y, g1.z, g1.w };
        float m1 = 0.f, m2 = 0.f, m3 = 0.f;
        #pragma unroll
        for (int g = 0; g < 8; g++) {
            float tt = d[g] * d[g];
            m1 += d[g];
            m2 += tt;
            m3 = fmaf(tt, d[g], m3);
        }
        __nv_bfloat16* br = Bs + (KC * il) * BPITCH + o;
        br[0 * BPITCH] = wv[k];
        br[1 * BPITCH] = __float2bfloat16(m1);
        br[2 * BPITCH] = __float2bfloat16(m2);
        br[3 * BPITCH] = __float2bfloat16(m3);
        br[4 * BPITCH] = __float2bfloat16(8.0f);
    }
    __syncthreads();

    // ---- GEMM [16 x 80] @ [80 x 32]; warp owns n = 8*warp..+8; 5 k-steps ----
    float c0 = 0.f, c1 = 0.f, c2 = 0.f, c3 = 0.f;
    const uint32_t as_base = (uint32_t)__cvta_generic_to_shared(As);
    const uint32_t bs_base = (uint32_t)__cvta_generic_to_shared(Bs);
    const int arow = lane & 15, asel = (lane >> 4) * 8;
    const int brow = lane & 15;

    #pragma unroll
    for (int ks = 0; ks < BROWS / 16; ks++) {
        uint32_t a0, a1, a2, a3, b0, b1;
        uint32_t aaddr = as_base + (uint32_t)((arow * APITCH + ks * 16 + asel) * 2);
        uint32_t baddr = bs_base + (uint32_t)(((ks * 16 + brow) * BPITCH + warp * 8) * 2);
        asm volatile("ldmatrix.sync.aligned.m8n8.x4.shared.b16 {%0,%1,%2,%3}, [%4];"
                     : "=r"(a0), "=r"(a1), "=r"(a2), "=r"(a3) : "r"(aaddr));
        asm volatile("ldmatrix.sync.aligned.m8n8.x2.trans.shared.b16 {%0,%1}, [%2];"
                     : "=r"(b0), "=r"(b1) : "r"(baddr));
        asm volatile("mma.sync.aligned.m16n8k16.row.col.f32.bf16.bf16.f32 "
                     "{%0,%1,%2,%3}, {%4,%5,%6,%7}, {%8,%9}, {%0,%1,%2,%3};"
                     : "+f"(c0), "+f"(c1), "+f"(c2), "+f"(c3)
                     : "r"(a0), "r"(a1), "r"(a2), "r"(a3), "r"(b0), "r"(b1));
    }

    // Epilogue: m16n8 acc layout -> atomicAdd into out[b][o].
    const int g = lane >> 2, tg = lane & 3;
    const int oc = o0 + warp * 8 + tg * 2;
    atomicAdd(out + g * OUT_ + oc,           c0);
    atomicAdd(out + g * OUT_ + oc + 1,       c1);
    atomicAdd(out + (g + 8) * OUT_ + oc,     c2);
    atomicAdd(out + (g + 8) * OUT_ + oc + 1, c3);
}

// ---------------- launch ----------------
extern "C" void kernel_launch(void* const* d_in, const int* in_sizes, int n_in,
                              void* d_out, int out_size)
{
    const float* x    = (const float*)d_in[0];   // [B, IN]
    const float* w    = (const float*)d_in[1];   // [OUT, IN]
    const float* grid = (const float*)d_in[2];   // [IN, OUT, G]
    float* out = (float*)d_out;                  // [B, OUT]

    kan_prep_kernel<<<1104, 256>>>(x, w, out);
    kan_mma_kernel<<<dim3(OUT_ / OTILE, IN_ / ITILE), 128>>>(grid, out);
}

// round 15
// speedup vs baseline: 1.1544x; 1.1544x over previous
#include <cuda_runtime.h>
#include <cuda_bf16.h>
#include <cstdint>

// KANSplineLayer via tensor cores, double-buffered bulk cp.async streaming.
// Order-3 Taylor: sum_g sigmoid(x+d_g) ~= 8*s + s'*m1 + (s''/2)*m2 + (s'''/6)*m3.
// One GEMM: out[b,o] = sum_{i,c} A[b,5i+c] * Bm[5i+c,o],
//   A  = (x, s', s''/2, s'''/6, s)   per (b,i)  [prep kernel, bf16]
//   Bm = (W^T[i,o], m1, m2, m3, 8)   per (i,o)  [built in smem from grid stream]
// R15: each CTA owns TWO 16KB grid tiles in separate commit groups; tile1's
// copy streams while tile0 computes -> loads stay in flight across the whole
// CTA lifetime (R14 was one-shot: issue, dead-wait, load-free tail).

#define B_   16
#define IN_  1024
#define OUT_ 1024
#define G_   8
#define KC   5
#define AK   (KC * IN_)           // 5120
#define ITILE 16
#define OTILE 32
#define NTILE 2                   // i-tiles per CTA
#define BROWS (KC * ITILE)        // 80
#define APITCH BROWS
#define BPITCH 40

__device__ __align__(16) __nv_bfloat16 Wt_g[IN_ * OUT_];  // W^T bf16 (2MB)
__device__ __align__(16) __nv_bfloat16 A_g[B_ * AK];      // A matrix (160KB)

// ---------------- Kernel 1: prep (W transpose->bf16, A build, out zero) ----------------
__global__ __launch_bounds__(256) void kan_prep_kernel(
    const float* __restrict__ x, const float* __restrict__ w, float* __restrict__ out)
{
    const int bx = blockIdx.x, t = threadIdx.x;
    if (bx < 1024) {                       // W transpose: 32x32 tiles
        __shared__ float tile[32][33];
        const int tio = bx & 31, too = bx >> 5;
        const int tx = t & 31, ty = t >> 5;
        #pragma unroll
        for (int k = 0; k < 4; k++)
            tile[ty + 8 * k][tx] = w[(size_t)(too * 32 + ty + 8 * k) * IN_ + tio * 32 + tx];
        __syncthreads();
        #pragma unroll
        for (int k = 0; k < 4; k++)
            Wt_g[(size_t)(tio * 32 + ty + 8 * k) * OUT_ + too * 32 + tx] =
                __float2bfloat16(tile[tx][ty + 8 * k]);
    } else if (bx < 1088) {                // A build: 64 CTAs x 256 = 16384 (b,i)
        int idx = (bx - 1024) * 256 + t;
        int b = idx >> 10, i = idx & 1023;
        float xv = x[b * IN_ + i];
        float s  = __fdividef(1.f, 1.f + __expf(-xv));
        float d1 = s * (1.f - s);
        float om2s = 1.f - 2.f * s;
        float p6 = fmaf(6.f * s, s - 1.f, 1.f);
        __nv_bfloat16* ap = A_g + (size_t)b * AK + KC * i;
        ap[0] = __float2bfloat16(xv);
        ap[1] = __float2bfloat16(d1);
        ap[2] = __float2bfloat16(0.5f * d1 * om2s);
        ap[3] = __float2bfloat16((1.f / 6.f) * d1 * p6);
        ap[4] = __float2bfloat16(s);
    } else {                               // zero out: 16 CTAs x 256 float4
        int idx = (bx - 1088) * 256 + t;
        reinterpret_cast<float4*>(out)[idx] = make_float4(0.f, 0.f, 0.f, 0.f);
    }
}

// ---------------- Kernel 2: double-buffered stream -> moments -> mma -> atomicAdd ----------------
__global__ __launch_bounds__(128, 5) void kan_mma_kernel(
    const float* __restrict__ grid, float* __restrict__ out)
{
    __shared__ __align__(16) float4        Gs[NTILE][ITILE * OTILE * 2]; // 2 x 16KB
    __shared__ __align__(16) __nv_bfloat16 As[NTILE][B_ * APITCH];      // 2 x 2.5KB
    __shared__ __align__(16) __nv_bfloat16 Bs[BROWS * BPITCH];          // 6.4KB (reused)

    const int t = threadIdx.x, lane = t & 31, warp = t >> 5;
    const int o0 = blockIdx.x * OTILE;
    const int ib = blockIdx.y * (NTILE * ITILE);      // first i of this CTA

    // ---- issue BOTH tiles' copies up front, one commit group per tile ----
    #pragma unroll
    for (int tile = 0; tile < NTILE; tile++) {
        unsigned gdst = (unsigned)__cvta_generic_to_shared(Gs[tile]);
        const float* gsrc0 = grid + ((size_t)(ib + tile * ITILE) * OUT_ + o0) * G_;
        #pragma unroll
        for (int k = 0; k < 8; k++) {                 // 1024 chunks of 16B
            int c   = t + 128 * k;
            int row = c >> 6, col = c & 63;
            const float* src = gsrc0 + (size_t)row * (OUT_ * G_) + col * 4;
            asm volatile("cp.async.cg.shared.global [%0], [%1], 16;"
                         :: "r"(gdst + c * 16), "l"(src));
        }
        unsigned adst = (unsigned)__cvta_generic_to_shared(As[tile]);
        #pragma unroll
        for (int k = 0; k < 2; k++) {                 // 160 chunks of 16B
            int c = t + 128 * k;
            if (c < 160) {
                int r = c / 10, col = c % 10;
                const __nv_bfloat16* src =
                    A_g + (size_t)r * AK + (size_t)(ib + tile * ITILE) * KC + col * 8;
                asm volatile("cp.async.cg.shared.global [%0], [%1], 16;"
                             :: "r"(adst + c * 16), "l"(src));
            }
        }
        asm volatile("cp.async.commit_group;" ::);
    }

    // W values while copies fly (coalesced: warp reads one Wt row, 32 cols).
    __nv_bfloat16 wv[NTILE][4];
    #pragma unroll
    for (int tile = 0; tile < NTILE; tile++)
        #pragma unroll
        for (int k = 0; k < 4; k++) {
            int il = warp + 4 * k;                    // (t+128k)>>5
            wv[tile][k] = Wt_g[(size_t)(ib + tile * ITILE + il) * OUT_ + o0 + lane];
        }

    float c0 = 0.f, c1 = 0.f, c2 = 0.f, c3 = 0.f;
    const uint32_t bs_base = (uint32_t)__cvta_generic_to_shared(Bs);
    const int arow = lane & 15, asel = (lane >> 4) * 8;
    const int brow = lane & 15;

    #pragma unroll
    for (int tile = 0; tile < NTILE; tile++) {
        if (tile == 0) asm volatile("cp.async.wait_group 1;" ::);
        else           asm volatile("cp.async.wait_group 0;" ::);
        __syncthreads();                              // tile data visible; Bs reusable

        // moments from smem -> Bs (4 (i,o) pairs per thread)
        #pragma unroll
        for (int k = 0; k < 4; k++) {
            int idx = t + 128 * k;
            int il = idx >> 5, o = idx & 31;
            float4 g0 = Gs[tile][il * 64 + o * 2], g1 = Gs[tile][il * 64 + o * 2 + 1];
            float d[8] = { g0.x, g0.y, g0.z, g0.w, g1.x, g1.y, g1.z, g1.w };
            float m1 = 0.f, m2 = 0.f, m3 = 0.f;
            #pragma unroll
            for (int g = 0; g < 8; g++) {
                float tt = d[g] * d[g];
                m1 += d[g];
                m2 += tt;
                m3 = fmaf(tt, d[g], m3);
            }
            __nv_bfloat16* br = Bs + (KC * il) * BPITCH + o;
            br[0 * BPITCH] = wv[tile][k];
            br[1 * BPITCH] = __float2bfloat16(m1);
            br[2 * BPITCH] = __float2bfloat16(m2);
            br[3 * BPITCH] = __float2bfloat16(m3);
            br[4 * BPITCH] = __float2bfloat16(8.0f);
        }
        __syncthreads();

        // GEMM [16 x 80] @ [80 x 32]; warp owns n = 8*warp..+8; 5 k-steps
        const uint32_t as_base = (uint32_t)__cvta_generic_to_shared(As[tile]);
        #pragma unroll
        for (int ks = 0; ks < BROWS / 16; ks++) {
            uint32_t a0, a1, a2, a3, b0, b1;
            uint32_t aaddr = as_base + (uint32_t)((arow * APITCH + ks * 16 + asel) * 2);
            uint32_t baddr = bs_base + (uint32_t)(((ks * 16 + brow) * BPITCH + warp * 8) * 2);
            asm volatile("ldmatrix.sync.aligned.m8n8.x4.shared.b16 {%0,%1,%2,%3}, [%4];"
                         : "=r"(a0), "=r"(a1), "=r"(a2), "=r"(a3) : "r"(aaddr));
            asm volatile("ldmatrix.sync.aligned.m8n8.x2.trans.shared.b16 {%0,%1}, [%2];"
                         : "=r"(b0), "=r"(b1) : "r"(baddr));
            asm volatile("mma.sync.aligned.m16n8k16.row.col.f32.bf16.bf16.f32 "
                         "{%0,%1,%2,%3}, {%4,%5,%6,%7}, {%8,%9}, {%0,%1,%2,%3};"
                         : "+f"(c0), "+f"(c1), "+f"(c2), "+f"(c3)
                         : "r"(a0), "r"(a1), "r"(a2), "r"(a3), "r"(b0), "r"(b1));
        }
        __syncthreads();                              // all warps done reading Bs
    }

    // Epilogue once: m16n8 acc layout -> atomicAdd into out[b][o].
    const int g = lane >> 2, tg = lane & 3;
    const int oc = o0 + warp * 8 + tg * 2;
    atomicAdd(out + g * OUT_ + oc,           c0);
    atomicAdd(out + g * OUT_ + oc + 1,       c1);
    atomicAdd(out + (g + 8) * OUT_ + oc,     c2);
    atomicAdd(out + (g + 8) * OUT_ + oc + 1, c3);
}

// ---------------- launch ----------------
extern "C" void kernel_launch(void* const* d_in, const int* in_sizes, int n_in,
                              void* d_out, int out_size)
{
    const float* x    = (const float*)d_in[0];   // [B, IN]
    const float* w    = (const float*)d_in[1];   // [OUT, IN]
    const float* grid = (const float*)d_in[2];   // [IN, OUT, G]
    float* out = (float*)d_out;                  // [B, OUT]

    kan_prep_kernel<<<1104, 256>>>(x, w, out);
    kan_mma_kernel<<<dim3(OUT_ / OTILE, IN_ / (NTILE * ITILE)), 128>>>(grid, out);
}